// round 10
// baseline (speedup 1.0000x reference)
#include <cuda_runtime.h>
#include <cuda_bf16.h>
#include <cstdint>

#define LL   2048
#define BB   2
#define DMODEL 512
#define HH   8
#define DKK  64
#define NT   4096   // BB*LL
#define HB   16     // HH*BB

// ---------------- scratch (device globals; no allocation allowed) ----------------
__device__ __nv_bfloat16 g_qhb[HB * LL * DKK];  // [hb][l][d] bf16, pre-scaled 1/64
__device__ __nv_bfloat16 g_khb[HB * LL * DKK];
__device__ __nv_bfloat16 g_vhb[HB * LL * DKK];
__device__ __nv_bfloat16 g_ctxbf[NT * DMODEL];  // ctx bf16 [b*L+l][h*64+d]
__device__ float g_linv[HB * LL];               // 1 / row sumexp

// ---------------- helpers ----------------
__device__ __forceinline__ uint32_t smem_u32(const void* p) {
    uint32_t a;
    asm("{ .reg .u64 t; cvta.to.shared.u64 t, %1; cvt.u32.u64 %0, t; }" : "=r"(a) : "l"(p));
    return a;
}
__device__ __forceinline__ uint32_t bf16x2(float lo, float hi) {
    uint32_t r;
    asm("cvt.rn.bf16x2.f32 %0, %1, %2;" : "=r"(r) : "f"(hi), "f"(lo));
    return r;
}
__device__ __forceinline__ void ldsm4(uint32_t* r, uint32_t addr) {
    asm volatile("ldmatrix.sync.aligned.m8n8.x4.shared.b16 {%0,%1,%2,%3}, [%4];"
                 : "=r"(r[0]), "=r"(r[1]), "=r"(r[2]), "=r"(r[3]) : "r"(addr));
}
__device__ __forceinline__ void ldsm4t(uint32_t* r, uint32_t addr) {
    asm volatile("ldmatrix.sync.aligned.m8n8.x4.trans.shared.b16 {%0,%1,%2,%3}, [%4];"
                 : "=r"(r[0]), "=r"(r[1]), "=r"(r[2]), "=r"(r[3]) : "r"(addr));
}
__device__ __forceinline__ void mma_bf16(float* c, const uint32_t* a, uint32_t b0, uint32_t b1) {
    asm volatile(
        "mma.sync.aligned.m16n8k16.row.col.f32.bf16.bf16.f32 "
        "{%0,%1,%2,%3}, {%4,%5,%6,%7}, {%8,%9}, {%0,%1,%2,%3};"
        : "+f"(c[0]), "+f"(c[1]), "+f"(c[2]), "+f"(c[3])
        : "r"(a[0]), "r"(a[1]), "r"(a[2]), "r"(a[3]), "r"(b0), "r"(b1));
}

// =====================================================================
// Kernel 1: fused QKV projection via bf16 mma.
// CTA: 64 rows x 128 cols, K in chunks of 64. 8 warps, 16m x 64n.
// =====================================================================
__global__ __launch_bounds__(256) void proj_kernel(
    const float* __restrict__ qin, const float* __restrict__ kin, const float* __restrict__ vin,
    const float* __restrict__ Wq, const float* __restrict__ bq,
    const float* __restrict__ Wk, const float* __restrict__ bk,
    const float* __restrict__ Wv, const float* __restrict__ bv)
{
    __shared__ __nv_bfloat16 As[64][72];    // X chunk, [m][k]
    __shared__ __nv_bfloat16 Ws[64][136];   // W chunk, [k][n]

    const int z = blockIdx.z;
    const float* X    = (z == 0) ? qin : (z == 1) ? kin : vin;
    const float* W    = (z == 0) ? Wq  : (z == 1) ? Wk  : Wv;
    const float* bias = (z == 0) ? bq  : (z == 1) ? bk  : bv;
    __nv_bfloat16* outp = (z == 0) ? g_qhb : (z == 1) ? g_khb : g_vhb;
    const float scale = (z == 0) ? (1.0f / 64.0f) : 1.0f;

    const int row0 = blockIdx.y * 64;
    const int col0 = blockIdx.x * 128;
    const int t = threadIdx.x, w = t >> 5, l = t & 31;
    const int qw = (w >> 1) * 16;
    const int nw = (w & 1) * 64;

    float acc[8][4];
#pragma unroll
    for (int nt = 0; nt < 8; nt++)
#pragma unroll
        for (int e = 0; e < 4; e++) acc[nt][e] = 0.0f;

    for (int k0 = 0; k0 < DMODEL; k0 += 64) {
#pragma unroll
        for (int p = 0; p < 4; p++) {
            int fi = t + p * 256;
            int row = fi >> 4, c4 = fi & 15;
            float4 f = *(const float4*)(X + (size_t)(row0 + row) * DMODEL + k0 + c4 * 4);
            uint2 pk = {bf16x2(f.x, f.y), bf16x2(f.z, f.w)};
            *(uint2*)&As[row][c4 * 4] = pk;
        }
#pragma unroll
        for (int p = 0; p < 8; p++) {
            int fi = t + p * 256;
            int krow = fi >> 5, c4 = fi & 31;
            float4 f = *(const float4*)(W + (size_t)(k0 + krow) * DMODEL + col0 + c4 * 4);
            uint2 pk = {bf16x2(f.x, f.y), bf16x2(f.z, f.w)};
            *(uint2*)&Ws[krow][c4 * 4] = pk;
        }
        __syncthreads();

#pragma unroll
        for (int d0 = 0; d0 < 64; d0 += 16) {
            uint32_t a[4];
            ldsm4(a, smem_u32(&As[qw + (l & 15)][d0 + (l >> 4) * 8]));
#pragma unroll
            for (int ntp = 0; ntp < 4; ntp++) {
                uint32_t bfr[4];
                int krow = d0 + (l & 7) + 8 * ((l >> 3) & 1);
                ldsm4t(bfr, smem_u32(&Ws[krow][nw + ntp * 16 + 8 * (l >> 4)]));
                mma_bf16(acc[ntp * 2 + 0], a, bfr[0], bfr[1]);
                mma_bf16(acc[ntp * 2 + 1], a, bfr[2], bfr[3]);
            }
        }
        __syncthreads();
    }

    const int r0 = row0 + qw + (l >> 2);
    const int r1 = r0 + 8;
#pragma unroll
    for (int nt = 0; nt < 8; nt++) {
        int cg = col0 + nw + nt * 8 + (l & 3) * 2;
        int h = cg >> 6, d = cg & 63;
        float b0 = bias[cg], b1 = bias[cg + 1];
        float o00 = (acc[nt][0] + b0) * scale;
        float o01 = (acc[nt][1] + b1) * scale;
        float o10 = (acc[nt][2] + b0) * scale;
        float o11 = (acc[nt][3] + b1) * scale;
        *(uint32_t*)(outp + (size_t)((h * BB + (r0 >> 11)) * LL + (r0 & 2047)) * DKK + d) = bf16x2(o00, o01);
        *(uint32_t*)(outp + (size_t)((h * BB + (r1 >> 11)) * LL + (r1 & 2047)) * DKK + d) = bf16x2(o10, o11);
    }
}

// =====================================================================
// Kernel 2: pass 1 — row sums of exp(S) -> g_linv.
// CTA: 128 q rows, k chunks of 128. 8 warps, each full-width 16q x 128k.
// Row sums never leave the warp (quad shuffles only).
// =====================================================================
__global__ __launch_bounds__(256) void linv_kernel(const int* __restrict__ mask)
{
    __shared__ __nv_bfloat16 Qs[128][72];
    __shared__ __nv_bfloat16 Ks[128][72];

    const int hb = blockIdx.y;
    const int q0 = blockIdx.x * 128;
    const int bat = hb & 1;
    const int t = threadIdx.x, w = t >> 5, l = t & 31;
    const int qw = w * 16;

    const __nv_bfloat16* qb = g_qhb + (size_t)hb * LL * DKK + (size_t)q0 * DKK;
    const __nv_bfloat16* kb = g_khb + (size_t)hb * LL * DKK;
    const int* mb = mask + (size_t)bat * LL * LL;

#pragma unroll
    for (int p = 0; p < 4; p++) {
        int fi = t + p * 256;
        int row = fi >> 3, c8 = fi & 7;
        *(uint4*)&Qs[row][c8 * 8] = *(const uint4*)(qb + (size_t)row * DKK + c8 * 8);
    }

    float rs0 = 0.0f, rs1 = 0.0f;
    const int r0g = q0 + qw + (l >> 2);
    const int r1g = r0g + 8;

    for (int kt = 0; kt < 16; kt++) {
        const int k0 = kt * 128;
#pragma unroll
        for (int p = 0; p < 4; p++) {
            int fi = t + p * 256;
            int row = fi >> 3, c8 = fi & 7;
            *(uint4*)&Ks[row][c8 * 8] = *(const uint4*)(kb + (size_t)(k0 + row) * DKK + c8 * 8);
        }
        __syncthreads();

        float acc[16][4];
#pragma unroll
        for (int nt = 0; nt < 16; nt++)
#pragma unroll
            for (int e = 0; e < 4; e++) acc[nt][e] = 0.0f;

#pragma unroll
        for (int d0 = 0; d0 < 64; d0 += 16) {
            uint32_t a[4];
            ldsm4(a, smem_u32(&Qs[qw + (l & 15)][d0 + (l >> 4) * 8]));
#pragma unroll
            for (int ntp = 0; ntp < 8; ntp++) {
                uint32_t bfr[4];
                int nrow = ntp * 16 + (l & 7) + 8 * (l >> 4);
                ldsm4(bfr, smem_u32(&Ks[nrow][d0 + 8 * ((l >> 3) & 1)]));
                mma_bf16(acc[ntp * 2 + 0], a, bfr[0], bfr[1]);
                mma_bf16(acc[ntp * 2 + 1], a, bfr[2], bfr[3]);
            }
        }

#pragma unroll
        for (int nt = 0; nt < 16; nt++) {
            int c = k0 + nt * 8 + (l & 3) * 2;
            int2 m0 = *(const int2*)(mb + (size_t)r0g * LL + c);
            int2 m1 = *(const int2*)(mb + (size_t)r1g * LL + c);
            rs0 += (m0.x ? __expf(acc[nt][0]) : 0.0f) + (m0.y ? __expf(acc[nt][1]) : 0.0f);
            rs1 += (m1.x ? __expf(acc[nt][2]) : 0.0f) + (m1.y ? __expf(acc[nt][3]) : 0.0f);
        }
        __syncthreads();
    }

    rs0 += __shfl_xor_sync(0xffffffffu, rs0, 1);
    rs0 += __shfl_xor_sync(0xffffffffu, rs0, 2);
    rs1 += __shfl_xor_sync(0xffffffffu, rs1, 1);
    rs1 += __shfl_xor_sync(0xffffffffu, rs1, 2);
    if ((l & 3) == 0) {
        g_linv[hb * LL + r0g] = 1.0f / rs0;
        g_linv[hb * LL + r1g] = 1.0f / rs1;
    }
}

// =====================================================================
// Kernel 3: pass 2 — recompute S, P = mask*exp(S)*linv (write attn),
// accumulate ctx = P @ V (bf16 out).
// CTA: 128 q rows, k chunks of 64. 8 warps full-width (16q x 64).
// Ps ALIASES the Ks buffer: S-phase reads Ks -> barrier -> epilogue
// overwrites region with bf16 P -> barrier -> PV-phase reads as Ps.
// =====================================================================
__global__ __launch_bounds__(256) void pv2_kernel(const int* __restrict__ mask,
                                                  float* __restrict__ attn)
{
    __shared__ __nv_bfloat16 Qs[128][72];
    __shared__ __nv_bfloat16 PKs[128][72];  // rows 0..63 = Ks during S phase; all 128 = Ps after
    __shared__ __nv_bfloat16 Vs[64][72];

    const int hb = blockIdx.y;
    const int q0 = blockIdx.x * 128;
    const int bat = hb & 1;
    const int h = hb >> 1;
    const int t = threadIdx.x, w = t >> 5, l = t & 31;
    const int qw = w * 16;

    const __nv_bfloat16* qb = g_qhb + (size_t)hb * LL * DKK + (size_t)q0 * DKK;
    const __nv_bfloat16* kb = g_khb + (size_t)hb * LL * DKK;
    const __nv_bfloat16* vb = g_vhb + (size_t)hb * LL * DKK;
    const int* mb = mask + (size_t)bat * LL * LL;
    float* ab = attn + (size_t)hb * LL * LL;

#pragma unroll
    for (int p = 0; p < 4; p++) {
        int fi = t + p * 256;
        int row = fi >> 3, c8 = fi & 7;
        *(uint4*)&Qs[row][c8 * 8] = *(const uint4*)(qb + (size_t)row * DKK + c8 * 8);
    }

    const int r0g = q0 + qw + (l >> 2);
    const int r1g = r0g + 8;
    const float li0 = g_linv[hb * LL + r0g];
    const float li1 = g_linv[hb * LL + r1g];

    float acc_pv[8][4];
#pragma unroll
    for (int nt = 0; nt < 8; nt++)
#pragma unroll
        for (int e = 0; e < 4; e++) acc_pv[nt][e] = 0.0f;

    for (int s = 0; s < 32; s++) {
        const int k0 = s * 64;
        // load K (into PKs rows 0..63) and V
#pragma unroll
        for (int p = 0; p < 2; p++) {
            int fi = t + p * 256;
            int row = fi >> 3, c8 = fi & 7;
            *(uint4*)&PKs[row][c8 * 8] = *(const uint4*)(kb + (size_t)(k0 + row) * DKK + c8 * 8);
            *(uint4*)&Vs[row][c8 * 8]  = *(const uint4*)(vb + (size_t)(k0 + row) * DKK + c8 * 8);
        }
        __syncthreads();

        // S phase: warp computes 16q x 64k
        float acc_s[8][4];
#pragma unroll
        for (int nt = 0; nt < 8; nt++)
#pragma unroll
            for (int e = 0; e < 4; e++) acc_s[nt][e] = 0.0f;

#pragma unroll
        for (int d0 = 0; d0 < 64; d0 += 16) {
            uint32_t a[4];
            ldsm4(a, smem_u32(&Qs[qw + (l & 15)][d0 + (l >> 4) * 8]));
#pragma unroll
            for (int ntp = 0; ntp < 4; ntp++) {
                uint32_t bfr[4];
                int nrow = ntp * 16 + (l & 7) + 8 * (l >> 4);
                ldsm4(bfr, smem_u32(&PKs[nrow][d0 + 8 * ((l >> 3) & 1)]));
                mma_bf16(acc_s[ntp * 2 + 0], a, bfr[0], bfr[1]);
                mma_bf16(acc_s[ntp * 2 + 1], a, bfr[2], bfr[3]);
            }
        }
        __syncthreads();   // all warps done reading Ks before P overwrites it

        // epilogue: P = mask * exp(S) * linv; write attn; stage Ps (aliasing Ks)
#pragma unroll
        for (int nt = 0; nt < 8; nt++) {
            int cl = nt * 8 + (l & 3) * 2;
            int c = k0 + cl;
            int2 m0 = *(const int2*)(mb + (size_t)r0g * LL + c);
            int2 m1 = *(const int2*)(mb + (size_t)r1g * LL + c);
            float p00 = m0.x ? __expf(acc_s[nt][0]) * li0 : 0.0f;
            float p01 = m0.y ? __expf(acc_s[nt][1]) * li0 : 0.0f;
            float p10 = m1.x ? __expf(acc_s[nt][2]) * li1 : 0.0f;
            float p11 = m1.y ? __expf(acc_s[nt][3]) * li1 : 0.0f;
            float2 w0 = {p00, p01}, w1 = {p10, p11};
            *(float2*)(ab + (size_t)r0g * LL + c) = w0;
            *(float2*)(ab + (size_t)r1g * LL + c) = w1;
            *(uint32_t*)&PKs[qw + (l >> 2)][cl]     = bf16x2(p00, p01);
            *(uint32_t*)&PKs[qw + 8 + (l >> 2)][cl] = bf16x2(p10, p11);
        }
        __syncthreads();

        // PV phase: warp accumulates 16q x 64d over this 64-k chunk
#pragma unroll
        for (int kk0 = 0; kk0 < 64; kk0 += 16) {
            uint32_t a[4];
            ldsm4(a, smem_u32(&PKs[qw + (l & 15)][kk0 + (l >> 4) * 8]));
#pragma unroll
            for (int ntp = 0; ntp < 4; ntp++) {
                uint32_t bfr[4];
                int krow = kk0 + (l & 7) + 8 * ((l >> 3) & 1);
                ldsm4t(bfr, smem_u32(&Vs[krow][ntp * 16 + 8 * (l >> 4)]));
                mma_bf16(acc_pv[ntp * 2 + 0], a, bfr[0], bfr[1]);
                mma_bf16(acc_pv[ntp * 2 + 1], a, bfr[2], bfr[3]);
            }
        }
        __syncthreads();   // before next chunk load overwrites PKs/Vs
    }

    // ctx epilogue (bf16)
#pragma unroll
    for (int nt = 0; nt < 8; nt++) {
        int c = h * 64 + nt * 8 + (l & 3) * 2;
        *(uint32_t*)(g_ctxbf + (size_t)(bat * LL + r0g) * DMODEL + c) = bf16x2(acc_pv[nt][0], acc_pv[nt][1]);
        *(uint32_t*)(g_ctxbf + (size_t)(bat * LL + r1g) * DMODEL + c) = bf16x2(acc_pv[nt][2], acc_pv[nt][3]);
    }
}

// =====================================================================
// Kernel 4: out = ctx(bf16) @ Wo + bo + residual(q), bf16 mma.
// =====================================================================
__global__ __launch_bounds__(256) void outproj_kernel(
    const float* __restrict__ resid, const float* __restrict__ Wo,
    const float* __restrict__ bo, float* __restrict__ out)
{
    __shared__ __nv_bfloat16 As[64][72];
    __shared__ __nv_bfloat16 Ws[64][136];

    const int row0 = blockIdx.y * 64;
    const int col0 = blockIdx.x * 128;
    const int t = threadIdx.x, w = t >> 5, l = t & 31;
    const int qw = (w >> 1) * 16;
    const int nw = (w & 1) * 64;

    float acc[8][4];
#pragma unroll
    for (int nt = 0; nt < 8; nt++)
#pragma unroll
        for (int e = 0; e < 4; e++) acc[nt][e] = 0.0f;

    for (int k0 = 0; k0 < DMODEL; k0 += 64) {
#pragma unroll
        for (int p = 0; p < 2; p++) {
            int fi = t + p * 256;
            int row = fi >> 3, c8 = fi & 7;
            *(uint4*)&As[row][c8 * 8] =
                *(const uint4*)(g_ctxbf + (size_t)(row0 + row) * DMODEL + k0 + c8 * 8);
        }
#pragma unroll
        for (int p = 0; p < 8; p++) {
            int fi = t + p * 256;
            int krow = fi >> 5, c4 = fi & 31;
            float4 f = *(const float4*)(Wo + (size_t)(k0 + krow) * DMODEL + col0 + c4 * 4);
            uint2 pk = {bf16x2(f.x, f.y), bf16x2(f.z, f.w)};
            *(uint2*)&Ws[krow][c4 * 4] = pk;
        }
        __syncthreads();

#pragma unroll
        for (int d0 = 0; d0 < 64; d0 += 16) {
            uint32_t a[4];
            ldsm4(a, smem_u32(&As[qw + (l & 15)][d0 + (l >> 4) * 8]));
#pragma unroll
            for (int ntp = 0; ntp < 4; ntp++) {
                uint32_t bfr[4];
                int krow = d0 + (l & 7) + 8 * ((l >> 3) & 1);
                ldsm4t(bfr, smem_u32(&Ws[krow][nw + ntp * 16 + 8 * (l >> 4)]));
                mma_bf16(acc[ntp * 2 + 0], a, bfr[0], bfr[1]);
                mma_bf16(acc[ntp * 2 + 1], a, bfr[2], bfr[3]);
            }
        }
        __syncthreads();
    }

    const int r0 = row0 + qw + (l >> 2);
    const int r1 = r0 + 8;
#pragma unroll
    for (int nt = 0; nt < 8; nt++) {
        int cg = col0 + nw + nt * 8 + (l & 3) * 2;
        float b0 = bo[cg], b1 = bo[cg + 1];
        float2 x0 = *(const float2*)(resid + (size_t)r0 * DMODEL + cg);
        float2 x1 = *(const float2*)(resid + (size_t)r1 * DMODEL + cg);
        float2 o0 = {acc[nt][0] + b0 + x0.x, acc[nt][1] + b1 + x0.y};
        float2 o1 = {acc[nt][2] + b0 + x1.x, acc[nt][3] + b1 + x1.y};
        *(float2*)(out + (size_t)r0 * DMODEL + cg) = o0;
        *(float2*)(out + (size_t)r1 * DMODEL + cg) = o1;
    }
}

// =====================================================================
extern "C" void kernel_launch(void* const* d_in, const int* in_sizes, int n_in,
                              void* d_out, int out_size)
{
    const float* q    = (const float*)d_in[0];
    const float* k    = (const float*)d_in[1];
    const float* v    = (const float*)d_in[2];
    const int*   mask = (const int*)  d_in[3];
    const float* Wq   = (const float*)d_in[4];
    const float* bq   = (const float*)d_in[5];
    const float* Wk   = (const float*)d_in[6];
    const float* bk   = (const float*)d_in[7];
    const float* Wv   = (const float*)d_in[8];
    const float* bv   = (const float*)d_in[9];
    const float* Wo   = (const float*)d_in[10];
    const float* bo   = (const float*)d_in[11];

    float* out  = (float*)d_out;
    float* attn = out + (size_t)NT * DMODEL;

    proj_kernel<<<dim3(4, 64, 3), 256>>>(q, k, v, Wq, bq, Wk, bk, Wv, bv);
    linv_kernel<<<dim3(16, 16), 256>>>(mask);
    pv2_kernel<<<dim3(16, 16), 256>>>(mask, attn);
    outproj_kernel<<<dim3(4, 64), 256>>>(q, Wo, bo, out);
}